// round 13
// baseline (speedup 1.0000x reference)
#include <cuda_runtime.h>
#include <cuda_fp16.h>
#include <math.h>
#include <stdint.h>

// Problem constants (fixed by setup_inputs)
#define NV 16384
#define GRP 32
#define NGROUPS 512
#define D 256
#define NH 8
#define HD 32
#define DI 1024
#define D_QKV 768
#define LN_EPS 1e-12f

// ---------------- scratch (device globals; no allocation allowed) ----------
__device__ __half g_X16[NV * D];
__device__ __half g_qkv16[NV * D_QKV];
__device__ __half g_att16[NV * D];
__device__ __half g_pre16[NV * D];
__device__ __half g_inter16[NV * DI];
__device__ __half g_Wqkv16[D_QKV * D];
__device__ __half g_Wo16[D * D];
__device__ __half g_Wi16[DI * D];
__device__ __half g_W216[D * DI];

// ---------------- helpers ---------------------------------------------------
__device__ __forceinline__ uint32_t smem_u32(const void* p) {
    uint32_t a;
    asm("{ .reg .u64 t; cvta.to.shared.u64 t, %1; cvt.u32.u64 %0, t; }" : "=r"(a) : "l"(p));
    return a;
}
__device__ __forceinline__ uint32_t sw128(uint32_t x) { return x ^ ((x >> 3) & 0x70); }

#define LDSM4(r0, r1, r2, r3, addr) \
    asm volatile("ldmatrix.sync.aligned.m8n8.x4.shared.b16 {%0,%1,%2,%3}, [%4];" \
                 : "=r"(r0), "=r"(r1), "=r"(r2), "=r"(r3) : "r"(addr))

#define LDSM4T(r0, r1, r2, r3, addr) \
    asm volatile("ldmatrix.sync.aligned.m8n8.x4.trans.shared.b16 {%0,%1,%2,%3}, [%4];" \
                 : "=r"(r0), "=r"(r1), "=r"(r2), "=r"(r3) : "r"(addr))

#define MMA16816(d, a, b) \
    asm volatile("mma.sync.aligned.m16n8k16.row.col.f32.f16.f16.f32 " \
                 "{%0,%1,%2,%3}, {%4,%5,%6,%7}, {%8,%9}, {%0,%1,%2,%3};" \
                 : "+f"((d)[0]), "+f"((d)[1]), "+f"((d)[2]), "+f"((d)[3]) \
                 : "r"((a)[0]), "r"((a)[1]), "r"((a)[2]), "r"((a)[3]), \
                   "r"((b)[0]), "r"((b)[1]))

__device__ __forceinline__ void cpasync16(uint32_t daddr, const void* g) {
    asm volatile("cp.async.cg.shared.global [%0], [%1], 16;" :: "r"(daddr), "l"(g));
}

// ---------------- prep: weight transposes + X conversion, one launch --------
__global__ void __launch_bounds__(256)
prep_kernel(const float* __restrict__ x,
            const float* __restrict__ Wq, const float* __restrict__ Wo,
            const float* __restrict__ Wi, const float* __restrict__ W2,
            __half* __restrict__ X16,
            __half* __restrict__ oq, __half* __restrict__ oo,
            __half* __restrict__ oi, __half* __restrict__ o2)
{
    int b = blockIdx.x;
    if (b >= 768) {
        const int i = (b - 768) * 1024 + threadIdx.x * 4;
        float4 v = *(const float4*)(x + i);
        __half2 h0, h1;
        h0.x = __float2half_rn(v.x); h0.y = __float2half_rn(v.y);
        h1.x = __float2half_rn(v.z); h1.y = __float2half_rn(v.w);
        *(__half2*)(X16 + i)     = h0;
        *(__half2*)(X16 + i + 2) = h1;
        return;
    }
    __shared__ float t[32][33];
    const float* W; __half* o; int K, N;
    if (b < 192)      { W = Wq; o = oq; K = D;  N = D_QKV; }
    else if (b < 256) { W = Wo; o = oo; K = D;  N = D;     b -= 192; }
    else if (b < 512) { W = Wi; o = oi; K = D;  N = DI;    b -= 256; }
    else              { W = W2; o = o2; K = DI; N = D;     b -= 512; }
    const int nt = N / 32;
    const int n0 = (b % nt) * 32, k0 = (b / nt) * 32;
    const int tx = threadIdx.x & 31, ty = threadIdx.x >> 5;
    for (int i = ty; i < 32; i += 8)
        t[i][tx] = W[(size_t)(k0 + i) * N + n0 + tx];
    __syncthreads();
    for (int i = ty; i < 32; i += 8)
        o[(size_t)(n0 + i) * K + k0 + tx] = __float2half_rn(t[tx][i]);
}

// ---------------- fp16 mma.sync GEMM (128x128 tile, fp16 out) ---------------
#define TILE_B 16384
#define CH_B   (2 * TILE_B)
#define OFF_BW TILE_B
#define STAGES 3
#define GSMEM  (STAGES * CH_B)

__device__ __forceinline__ void load_chunk(const __half* __restrict__ A,
                                           const __half* __restrict__ B,
                                           int bm, int bn, int K, int k0,
                                           uint32_t sbuf, int tid)
{
#pragma unroll
    for (int t = 0; t < 4; t++) {
        const int u = tid + t * 256;
        const int row = u >> 3, c = u & 7;
        const uint32_t off = sw128(row * 128 + c * 16);
        cpasync16(sbuf + off,          A + (size_t)(bm + row) * K + k0 + c * 8);
        cpasync16(sbuf + OFF_BW + off, B + (size_t)(bn + row) * K + k0 + c * 8);
    }
}

// EPI: 0 none, 2 gelu. Output fp16 only.
template <int EPI>
__global__ void __launch_bounds__(256)
gemm_mma(const __half* __restrict__ A16, const __half* __restrict__ W,
         __half* __restrict__ C16, int N, int K)
{
    extern __shared__ char smem[];
    const uint32_t sb = smem_u32(smem);
    const int tid = threadIdx.x;
    const int wid = tid >> 5, lane = tid & 31;
    const int bm = blockIdx.y * 128, bn = blockIdx.x * 128;
    const int wm = (wid & 3) * 32;
    const int wn = (wid >> 2) * 64;
    const int nch = K >> 6;

    float acc[2][8][4];
#pragma unroll
    for (int mi = 0; mi < 2; mi++)
#pragma unroll
        for (int ni = 0; ni < 8; ni++)
#pragma unroll
            for (int j = 0; j < 4; j++) acc[mi][ni][j] = 0.f;

    load_chunk(A16, W, bm, bn, K, 0, sb, tid);
    asm volatile("cp.async.commit_group;" ::: "memory");
    if (nch > 1) load_chunk(A16, W, bm, bn, K, 64, sb + CH_B, tid);
    asm volatile("cp.async.commit_group;" ::: "memory");

    for (int c = 0; c < nch; c++) {
        asm volatile("cp.async.wait_group 1;" ::: "memory");
        __syncthreads();
        if (c + 2 < nch)
            load_chunk(A16, W, bm, bn, K, (c + 2) * 64, sb + ((c + 2) % STAGES) * CH_B, tid);
        asm volatile("cp.async.commit_group;" ::: "memory");

        const uint32_t st = sb + (c % STAGES) * CH_B;
#pragma unroll
        for (int ks = 0; ks < 4; ks++) {
            const uint32_t cofs = ks * 32 + (lane >> 4) * 16;
            uint32_t a[2][4];
#pragma unroll
            for (int mi = 0; mi < 2; mi++) {
                const uint32_t ro = sw128((wm + mi * 16 + (lane & 15)) * 128 + cofs);
                LDSM4(a[mi][0], a[mi][1], a[mi][2], a[mi][3], st + ro);
            }
            uint32_t b[8][2];
#pragma unroll
            for (int np = 0; np < 4; np++) {
                const uint32_t ro = sw128((wn + np * 16 + (lane & 15)) * 128 + cofs);
                uint32_t r0, r1, r2, r3;
                LDSM4(r0, r1, r2, r3, st + OFF_BW + ro);
                b[np * 2][0] = r0; b[np * 2][1] = r2;
                b[np * 2 + 1][0] = r1; b[np * 2 + 1][1] = r3;
            }
#pragma unroll
            for (int mi = 0; mi < 2; mi++)
#pragma unroll
                for (int ni = 0; ni < 8; ni++)
                    MMA16816(acc[mi][ni], a[mi], b[ni]);
        }
        __syncthreads();
    }

#pragma unroll
    for (int mi = 0; mi < 2; mi++) {
#pragma unroll
        for (int ni = 0; ni < 8; ni++) {
            const int row0 = bm + wm + mi * 16 + (lane >> 2);
            const int col  = bn + wn + ni * 8 + (lane & 3) * 2;
#pragma unroll
            for (int h = 0; h < 2; h++) {
                const size_t gofs = (size_t)(row0 + h * 8) * N + col;
                float vx = acc[mi][ni][h * 2 + 0];
                float vy = acc[mi][ni][h * 2 + 1];
                if (EPI == 2) {
                    vx = 0.5f * vx * (1.f + erff(vx * 0.70710678118654752f));
                    vy = 0.5f * vy * (1.f + erff(vy * 0.70710678118654752f));
                }
                __half2 hh;
                hh.x = __float2half_rn(vx);
                hh.y = __float2half_rn(vy);
                *(__half2*)(C16 + gofs) = hh;
            }
        }
    }
}

// ---------------- LN1: persistent W-resident fused GEMM+residual+LN ---------
// pre16 = LN1(att @ Wo^T + x).  K = D = 256 fixed, N = 256.
// grid 128 CTAs, each handles 4 M-tiles of 32 rows. Wo resident in smem.
#define LN1_WB   131072                 // 256 rows x 256 K x 2B, in 4 chunk-tiles
#define LN1_SP   LN1_WB                 // partials after W
#define LN1_SMEM (LN1_WB + 32 * 8 * 2 * 4)

__global__ void __launch_bounds__(256, 1)
ln1_kernel(const __half* __restrict__ A16, const __half* __restrict__ W,
           const float* __restrict__ Rf,
           const float* __restrict__ g, const float* __restrict__ b,
           __half* __restrict__ Yh)
{
    extern __shared__ char smem[];
    const uint32_t sb = smem_u32(smem);
    const int tid = threadIdx.x;
    const int wid = tid >> 5, lane = tid & 31;
    const int qr = lane >> 2, qc = (lane & 3) * 2;
    const int WN = wid * 32;            // warp's 32-col slice

    // ---- load all of Wo into smem: 4 chunk-tiles of [256 rows x 128B] ----
#pragma unroll
    for (int t = 0; t < 32; t++) {
        const int u = tid + t * 256;    // 0..8191 16B-units
        const int chunk = u >> 11, within = u & 2047;
        const int row = within >> 3, c = within & 7;
        cpasync16(sb + chunk * 32768 + sw128(row * 128 + c * 16),
                  W + (size_t)row * 256 + chunk * 64 + c * 8);
    }
    asm volatile("cp.async.commit_group;" ::: "memory");
    asm volatile("cp.async.wait_group 0;" ::: "memory");
    __syncthreads();

    float* sp = (float*)(smem + LN1_SP);   // [32 rows][8 warps][2]

    for (int tile = blockIdx.x; tile < NV / 32; tile += 128) {
        const int bm = tile * 32;
        const __half* Abase = A16 + (size_t)bm * D;

        float acc[2][4][4];
#pragma unroll
        for (int mi = 0; mi < 2; mi++)
#pragma unroll
            for (int ni = 0; ni < 4; ni++)
#pragma unroll
                for (int j = 0; j < 4; j++) acc[mi][ni][j] = 0.f;

        // mainloop: 16 k-steps, A direct from gmem (L1-shared across warps),
        // B from resident smem W. No syncs, no waits.
#pragma unroll 4
        for (int ks = 0; ks < 16; ks++) {
            const int kc = ks * 16;
            uint32_t a[2][4];
#pragma unroll
            for (int mi = 0; mi < 2; mi++) {
                const __half* plo = Abase + (size_t)(mi * 16 + qr) * D + kc + qc;
                const __half* phi = plo + (size_t)8 * D;
                a[mi][0] = *(const uint32_t*)plo;
                a[mi][1] = *(const uint32_t*)phi;
                a[mi][2] = *(const uint32_t*)(plo + 8);
                a[mi][3] = *(const uint32_t*)(phi + 8);
            }
            const uint32_t chb = (ks >> 2) * 32768;
            const uint32_t cofs = (ks & 3) * 32 + (lane >> 4) * 16;
#pragma unroll
            for (int np = 0; np < 2; np++) {
                const uint32_t ro = chb + sw128((WN + np * 16 + (lane & 15)) * 128 + cofs);
                uint32_t r0, r1, r2, r3;
                LDSM4(r0, r1, r2, r3, sb + ro);
                uint32_t bb[2][2];
                bb[0][0] = r0; bb[0][1] = r2;
                bb[1][0] = r1; bb[1][1] = r3;
#pragma unroll
                for (int mi = 0; mi < 2; mi++)
#pragma unroll
                    for (int cc = 0; cc < 2; cc++)
                        MMA16816(acc[mi][np * 2 + cc], a[mi], bb[cc]);
            }
        }

        // residual add (fp32 x)
#pragma unroll
        for (int mi = 0; mi < 2; mi++)
#pragma unroll
            for (int h = 0; h < 2; h++) {
                const int row = mi * 16 + h * 8 + qr;
#pragma unroll
                for (int ni = 0; ni < 4; ni++) {
                    const int col = WN + ni * 8 + qc;
                    float2 f = *(const float2*)(Rf + (size_t)(bm + row) * D + col);
                    acc[mi][ni][h * 2 + 0] += f.x;
                    acc[mi][ni][h * 2 + 1] += f.y;
                }
            }

        // LN partials
#pragma unroll
        for (int mi = 0; mi < 2; mi++)
#pragma unroll
            for (int h = 0; h < 2; h++) {
                float s1 = 0.f, s2 = 0.f;
#pragma unroll
                for (int ni = 0; ni < 4; ni++) {
                    float vx = acc[mi][ni][h * 2], vy = acc[mi][ni][h * 2 + 1];
                    s1 += vx + vy;
                    s2 += vx * vx + vy * vy;
                }
#pragma unroll
                for (int o = 1; o < 4; o <<= 1) {
                    s1 += __shfl_xor_sync(0xffffffffu, s1, o);
                    s2 += __shfl_xor_sync(0xffffffffu, s2, o);
                }
                if ((lane & 3) == 0) {
                    const int row = mi * 16 + h * 8 + qr;
                    sp[(row * 8 + wid) * 2 + 0] = s1;
                    sp[(row * 8 + wid) * 2 + 1] = s2;
                }
            }
        __syncthreads();

        // normalize + store
#pragma unroll
        for (int mi = 0; mi < 2; mi++)
#pragma unroll
            for (int h = 0; h < 2; h++) {
                const int row = mi * 16 + h * 8 + qr;
                float s1 = 0.f, s2 = 0.f;
#pragma unroll
                for (int q = 0; q < 8; q++) {
                    s1 += sp[(row * 8 + q) * 2 + 0];
                    s2 += sp[(row * 8 + q) * 2 + 1];
                }
                const float mean = s1 * (1.0f / D);
                const float var  = s2 * (1.0f / D) - mean * mean;
                const float rstd = rsqrtf(var + LN_EPS);
#pragma unroll
                for (int ni = 0; ni < 4; ni++) {
                    const int col = WN + ni * 8 + qc;
                    const float2 gg = *(const float2*)(g + col);
                    const float2 bb = *(const float2*)(b + col);
                    const float ox = (acc[mi][ni][h * 2]     - mean) * rstd * gg.x + bb.x;
                    const float oy = (acc[mi][ni][h * 2 + 1] - mean) * rstd * gg.y + bb.y;
                    __half2 hh;
                    hh.x = __float2half_rn(ox);
                    hh.y = __float2half_rn(oy);
                    *(__half2*)(Yh + (size_t)(bm + row) * D + col) = hh;
                }
            }
        __syncthreads();
    }
}

// ---------------- LN2: fused GEMM + residual + LayerNorm, 64x256, K=1024 ----
#define LN_ATILE 8192
#define LN_CH (LN_ATILE + 32768)
#define LN_SMEM (2 * LN_CH + 64 * 4 * 2 * 4)

__device__ __forceinline__ void load_chunk_ln2(const __half* __restrict__ A,
                                               const __half* __restrict__ W,
                                               int bm, int K, int k0,
                                               uint32_t sbuf, int tid)
{
#pragma unroll
    for (int t = 0; t < 2; t++) {
        const int u = tid + t * 256;
        const int row = u >> 3, c = u & 7;
        cpasync16(sbuf + sw128(row * 128 + c * 16),
                  A + (size_t)(bm + row) * K + k0 + c * 8);
    }
#pragma unroll
    for (int t = 0; t < 8; t++) {
        const int u = tid + t * 256;
        const int row = u >> 3, c = u & 7;
        cpasync16(sbuf + LN_ATILE + sw128(row * 128 + c * 16),
                  W + (size_t)(row) * K + k0 + c * 8);
    }
}

__global__ void __launch_bounds__(256, 2)
ln2_kernel(const __half* __restrict__ A16, const __half* __restrict__ W,
           const __half* __restrict__ Rh,
           const float* __restrict__ g, const float* __restrict__ b,
           float* __restrict__ Y, int K)
{
    extern __shared__ char smem[];
    const uint32_t sb = smem_u32(smem);
    const int tid = threadIdx.x;
    const int wid = tid >> 5, lane = tid & 31;
    const int bm = blockIdx.x * 64;
    const int WM = (wid & 1) * 32;
    const int WN = (wid >> 1) * 64;
    const int wq = wid >> 1;
    const int nch = K >> 6;

    float acc[2][8][4];
#pragma unroll
    for (int mi = 0; mi < 2; mi++)
#pragma unroll
        for (int ni = 0; ni < 8; ni++)
#pragma unroll
            for (int j = 0; j < 4; j++) acc[mi][ni][j] = 0.f;

    load_chunk_ln2(A16, W, bm, K, 0, sb, tid);
    asm volatile("cp.async.commit_group;" ::: "memory");

    for (int c = 0; c < nch; c++) {
        if (c + 1 < nch) {
            load_chunk_ln2(A16, W, bm, K, (c + 1) * 64, sb + ((c + 1) & 1) * LN_CH, tid);
            asm volatile("cp.async.commit_group;" ::: "memory");
            asm volatile("cp.async.wait_group 1;" ::: "memory");
        } else {
            asm volatile("cp.async.wait_group 0;" ::: "memory");
        }
        __syncthreads();

        const uint32_t st = sb + (c & 1) * LN_CH;
#pragma unroll
        for (int ks = 0; ks < 4; ks++) {
            const uint32_t cofs = ks * 32 + (lane >> 4) * 16;
            uint32_t a[2][4];
#pragma unroll
            for (int mi = 0; mi < 2; mi++) {
                const uint32_t ro = sw128((WM + mi * 16 + (lane & 15)) * 128 + cofs);
                LDSM4(a[mi][0], a[mi][1], a[mi][2], a[mi][3], st + ro);
            }
#pragma unroll
            for (int np = 0; np < 4; np++) {
                const uint32_t ro = sw128((WN + np * 16 + (lane & 15)) * 128 + cofs);
                uint32_t r0, r1, r2, r3;
                LDSM4(r0, r1, r2, r3, st + LN_ATILE + ro);
                uint32_t bb[2][2];
                bb[0][0] = r0; bb[0][1] = r2;
                bb[1][0] = r1; bb[1][1] = r3;
#pragma unroll
                for (int mi = 0; mi < 2; mi++)
#pragma unroll
                    for (int cc = 0; cc < 2; cc++)
                        MMA16816(acc[mi][np * 2 + cc], a[mi], bb[cc]);
            }
        }
        __syncthreads();
    }

    // residual (fp16 pre)
#pragma unroll
    for (int mi = 0; mi < 2; mi++)
#pragma unroll
        for (int h = 0; h < 2; h++) {
            const int row = WM + mi * 16 + h * 8 + (lane >> 2);
#pragma unroll
            for (int ni = 0; ni < 8; ni++) {
                const int col = WN + ni * 8 + (lane & 3) * 2;
                float2 f = __half22float2(*(const __half2*)(Rh + (size_t)(bm + row) * D + col));
                acc[mi][ni][h * 2 + 0] += f.x;
                acc[mi][ni][h * 2 + 1] += f.y;
            }
        }

    float* sp = (float*)(smem + 2 * LN_CH);   // [64][4][2]
#pragma unroll
    for (int mi = 0; mi < 2; mi++)
#pragma unroll
        for (int h = 0; h < 2; h++) {
            float s1 = 0.f, s2 = 0.f;
#pragma unroll
            for (int ni = 0; ni < 8; ni++) {
                float vx = acc[mi][ni][h * 2], vy = acc[mi][ni][h * 2 + 1];
                s1 += vx + vy;
                s2 += vx * vx + vy * vy;
            }
#pragma unroll
            for (int o = 1; o < 4; o <<= 1) {
                s1 += __shfl_xor_sync(0xffffffffu, s1, o);
                s2 += __shfl_xor_sync(0xffffffffu, s2, o);
            }
            if ((lane & 3) == 0) {
                const int row = WM + mi * 16 + h * 8 + (lane >> 2);
                sp[(row * 4 + wq) * 2 + 0] = s1;
                sp[(row * 4 + wq) * 2 + 1] = s2;
            }
        }
    __syncthreads();

#pragma unroll
    for (int mi = 0; mi < 2; mi++)
#pragma unroll
        for (int h = 0; h < 2; h++) {
            const int row = WM + mi * 16 + h * 8 + (lane >> 2);
            float s1 = 0.f, s2 = 0.f;
#pragma unroll
            for (int q = 0; q < 4; q++) {
                s1 += sp[(row * 4 + q) * 2 + 0];
                s2 += sp[(row * 4 + q) * 2 + 1];
            }
            const float mean = s1 * (1.0f / D);
            const float var  = s2 * (1.0f / D) - mean * mean;
            const float rstd = rsqrtf(var + LN_EPS);
#pragma unroll
            for (int ni = 0; ni < 8; ni++) {
                const int col = WN + ni * 8 + (lane & 3) * 2;
                const float2 gg = *(const float2*)(g + col);
                const float2 bb = *(const float2*)(b + col);
                float2 f;
                f.x = (acc[mi][ni][h * 2]     - mean) * rstd * gg.x + bb.x;
                f.y = (acc[mi][ni][h * 2 + 1] - mean) * rstd * gg.y + bb.y;
                *(float2*)(Y + (size_t)(bm + row) * D + col) = f;
            }
        }
}

// ---------------- tensor-core block-diagonal attention ----------------------
__global__ void __launch_bounds__(256)
attn_kernel(const __half* __restrict__ qkv, __half* __restrict__ att16)
{
    __shared__ __half Vs[NH][32][40];

    const int grp = blockIdx.x;
    const int w = threadIdx.x >> 5, lane = threadIdx.x & 31;
    const __half* base = qkv + (size_t)grp * GRP * D_QKV + w * 96;

    {
        const uint4* src = (const uint4*)(base + (size_t)lane * D_QKV + 64);
        uint4* dst = (uint4*)&Vs[w][lane][0];
        dst[0] = src[0]; dst[1] = src[1]; dst[2] = src[2]; dst[3] = src[3];
    }

    const int qr = lane >> 2, qc = (lane & 3) * 2;

    uint32_t a[2][2][4];
#pragma unroll
    for (int mi = 0; mi < 2; mi++) {
        const __half* plo = base + (size_t)(mi * 16 + qr) * D_QKV;
        const __half* phi = base + (size_t)(mi * 16 + qr + 8) * D_QKV;
#pragma unroll
        for (int kk = 0; kk < 2; kk++) {
            a[mi][kk][0] = *(const uint32_t*)(plo + kk * 16 + qc);
            a[mi][kk][1] = *(const uint32_t*)(phi + kk * 16 + qc);
            a[mi][kk][2] = *(const uint32_t*)(plo + kk * 16 + qc + 8);
            a[mi][kk][3] = *(const uint32_t*)(phi + kk * 16 + qc + 8);
        }
    }
    uint32_t bk[4][2][2];
#pragma unroll
    for (int ni = 0; ni < 4; ni++) {
        const __half* pn = base + (size_t)(ni * 8 + qr) * D_QKV + 32;
#pragma unroll
        for (int kk = 0; kk < 2; kk++) {
            bk[ni][kk][0] = *(const uint32_t*)(pn + kk * 16 + qc);
            bk[ni][kk][1] = *(const uint32_t*)(pn + kk * 16 + qc + 8);
        }
    }

    float s[2][4][4];
#pragma unroll
    for (int mi = 0; mi < 2; mi++)
#pragma unroll
        for (int ni = 0; ni < 4; ni++) {
#pragma unroll
            for (int j = 0; j < 4; j++) s[mi][ni][j] = 0.f;
#pragma unroll
            for (int kk = 0; kk < 2; kk++)
                MMA16816(s[mi][ni], a[mi][kk], bk[ni][kk]);
        }

    const float scl = 0.17677669529663687f;
    uint32_t p[2][2][4];
    float inv_lo[2], inv_hi[2];
#pragma unroll
    for (int mi = 0; mi < 2; mi++) {
        float mlo = -1e30f, mhi = -1e30f;
#pragma unroll
        for (int ni = 0; ni < 4; ni++) {
#pragma unroll
            for (int j = 0; j < 4; j++) s[mi][ni][j] *= scl;
            mlo = fmaxf(mlo, fmaxf(s[mi][ni][0], s[mi][ni][1]));
            mhi = fmaxf(mhi, fmaxf(s[mi][ni][2], s[mi][ni][3]));
        }
#pragma unroll
        for (int o = 1; o < 4; o <<= 1) {
            mlo = fmaxf(mlo, __shfl_xor_sync(0xffffffffu, mlo, o));
            mhi = fmaxf(mhi, __shfl_xor_sync(0xffffffffu, mhi, o));
        }
        float slo = 0.f, shi = 0.f;
        float e[4][4];
#pragma unroll
        for (int ni = 0; ni < 4; ni++) {
            e[ni][0] = expf(s[mi][ni][0] - mlo);
            e[ni][1] = expf(s[mi][ni][1] - mlo);
            e[ni][2] = expf(s[mi][ni][2] - mhi);
            e[ni][3] = expf(s[mi][ni][3] - mhi);
            slo += e[ni][0] + e[ni][1];
            shi += e[ni][2] + e[ni][3];
        }
#pragma unroll
        for (int o = 1; o < 4; o <<= 1) {
            slo += __shfl_xor_sync(0xffffffffu, slo, o);
            shi += __shfl_xor_sync(0xffffffffu, shi, o);
        }
        inv_lo[mi] = 1.0f / slo;
        inv_hi[mi] = 1.0f / shi;
#pragma unroll
        for (int kk = 0; kk < 2; kk++) {
            __half2 h;
            h.x = __float2half_rn(e[2 * kk][0]);     h.y = __float2half_rn(e[2 * kk][1]);
            p[mi][kk][0] = *(uint32_t*)&h;
            h.x = __float2half_rn(e[2 * kk][2]);     h.y = __float2half_rn(e[2 * kk][3]);
            p[mi][kk][1] = *(uint32_t*)&h;
            h.x = __float2half_rn(e[2 * kk + 1][0]); h.y = __float2half_rn(e[2 * kk + 1][1]);
            p[mi][kk][2] = *(uint32_t*)&h;
            h.x = __float2half_rn(e[2 * kk + 1][2]); h.y = __float2half_rn(e[2 * kk + 1][3]);
            p[mi][kk][3] = *(uint32_t*)&h;
        }
    }

    __syncwarp();
    uint32_t bv[4][2][2];
#pragma unroll
    for (int kk = 0; kk < 2; kk++) {
#pragma unroll
        for (int ch = 0; ch < 2; ch++) {
            const int vrow = kk * 16 + ((lane >> 4) * 8) + (lane & 7);
            const int vcol = ch * 16 + ((lane >> 3) & 1) * 8;
            uint32_t r0, r1, r2, r3;
            LDSM4T(r0, r1, r2, r3, smem_u32(&Vs[w][vrow][vcol]));
            bv[ch * 2][kk][0] = r0;     bv[ch * 2][kk][1] = r2;
            bv[ch * 2 + 1][kk][0] = r1; bv[ch * 2 + 1][kk][1] = r3;
        }
    }

    float o[2][4][4];
#pragma unroll
    for (int mi = 0; mi < 2; mi++)
#pragma unroll
        for (int n2 = 0; n2 < 4; n2++) {
#pragma unroll
            for (int j = 0; j < 4; j++) o[mi][n2][j] = 0.f;
#pragma unroll
            for (int kk = 0; kk < 2; kk++)
                MMA16816(o[mi][n2], p[mi][kk], bv[n2][kk]);
        }

#pragma unroll
    for (int mi = 0; mi < 2; mi++) {
#pragma unroll
        for (int n2 = 0; n2 < 4; n2++) {
            const int col = w * HD + n2 * 8 + qc;
            const size_t rlo = (size_t)(grp * GRP + mi * 16 + qr) * D + col;
            const size_t rhi = rlo + 8 * D;
            __half2 h0, h1;
            h0.x = __float2half_rn(o[mi][n2][0] * inv_lo[mi]);
            h0.y = __float2half_rn(o[mi][n2][1] * inv_lo[mi]);
            h1.x = __float2half_rn(o[mi][n2][2] * inv_hi[mi]);
            h1.y = __float2half_rn(o[mi][n2][3] * inv_hi[mi]);
            *(__half2*)(att16 + rlo) = h0;
            *(__half2*)(att16 + rhi) = h1;
        }
    }
}

// ---------------- launch ----------------------------------------------------
extern "C" void kernel_launch(void* const* d_in, const int* in_sizes, int n_in,
                              void* d_out, int out_size)
{
    const float* x      = (const float*)d_in[0];
    const float* W_qkv  = (const float*)d_in[2];
    const float* W_o    = (const float*)d_in[3];
    const float* ln1_g  = (const float*)d_in[4];
    const float* ln1_b  = (const float*)d_in[5];
    const float* W_i    = (const float*)d_in[6];
    const float* W_out2 = (const float*)d_in[7];
    const float* ln2_g  = (const float*)d_in[8];
    const float* ln2_b  = (const float*)d_in[9];
    float* out = (float*)d_out;

    __half *X16, *qkv16, *att16, *pre16, *inter16;
    __half *Wq16, *Wo16, *Wi16, *W216;
    cudaGetSymbolAddress((void**)&X16, g_X16);
    cudaGetSymbolAddress((void**)&qkv16, g_qkv16);
    cudaGetSymbolAddress((void**)&att16, g_att16);
    cudaGetSymbolAddress((void**)&pre16, g_pre16);
    cudaGetSymbolAddress((void**)&inter16, g_inter16);
    cudaGetSymbolAddress((void**)&Wq16, g_Wqkv16);
    cudaGetSymbolAddress((void**)&Wo16, g_Wo16);
    cudaGetSymbolAddress((void**)&Wi16, g_Wi16);
    cudaGetSymbolAddress((void**)&W216, g_W216);

    cudaFuncSetAttribute(gemm_mma<0>, cudaFuncAttributeMaxDynamicSharedMemorySize, GSMEM);
    cudaFuncSetAttribute(gemm_mma<2>, cudaFuncAttributeMaxDynamicSharedMemorySize, GSMEM);
    cudaFuncSetAttribute(ln1_kernel, cudaFuncAttributeMaxDynamicSharedMemorySize, LN1_SMEM);
    cudaFuncSetAttribute(ln2_kernel, cudaFuncAttributeMaxDynamicSharedMemorySize, LN_SMEM);

    // 0) prep: weight transposes + X conversion (one launch)
    prep_kernel<<<768 + NV * D / 1024, 256>>>(x, W_qkv, W_o, W_i, W_out2,
                                              X16, Wq16, Wo16, Wi16, W216);

    // 1) qkv16 = X @ W_qkv        [16384, 768] fp16
    gemm_mma<0><<<dim3(D_QKV / 128, NV / 128), 256, GSMEM>>>(X16, Wq16, qkv16, D_QKV, D);
    // 2) attention -> att16 (tensor-core)
    attn_kernel<<<NGROUPS, 256>>>(qkv16, att16);
    // 3+4) pre16 = LN1(att @ W_o + X)   [persistent, W-resident]
    ln1_kernel<<<128, 256, LN1_SMEM>>>(att16, Wo16, x, ln1_g, ln1_b, pre16);
    // 5) inter16 = gelu(pre @ W_i)
    gemm_mma<2><<<dim3(DI / 128, NV / 128), 256, GSMEM>>>(pre16, Wi16, inter16, DI, D);
    // 6+7) out = LN2(inter @ W_out2 + pre16)
    ln2_kernel<<<NV / 64, 256, LN_SMEM>>>(inter16, W216, pre16, ln2_g, ln2_b, out, DI);
}

// round 14
// speedup vs baseline: 1.1065x; 1.1065x over previous
#include <cuda_runtime.h>
#include <cuda_fp16.h>
#include <math.h>
#include <stdint.h>

// Problem constants (fixed by setup_inputs)
#define NV 16384
#define GRP 32
#define NGROUPS 512
#define D 256
#define NH 8
#define HD 32
#define DI 1024
#define D_QKV 768
#define LN_EPS 1e-12f

// ---------------- scratch (device globals; no allocation allowed) ----------
__device__ __half g_X16[NV * D];
__device__ __half g_qkv16[NV * D_QKV];
__device__ __half g_pre16[NV * D];
__device__ __half g_inter16[NV * DI];
__device__ __half g_Wqkv16[D_QKV * D];
__device__ __half g_Wo16[D * D];
__device__ __half g_Wi16[DI * D];
__device__ __half g_W216[D * DI];

// ---------------- helpers ---------------------------------------------------
__device__ __forceinline__ uint32_t smem_u32(const void* p) {
    uint32_t a;
    asm("{ .reg .u64 t; cvta.to.shared.u64 t, %1; cvt.u32.u64 %0, t; }" : "=r"(a) : "l"(p));
    return a;
}
__device__ __forceinline__ uint32_t sw128(uint32_t x) { return x ^ ((x >> 3) & 0x70); }

#define LDSM4(r0, r1, r2, r3, addr) \
    asm volatile("ldmatrix.sync.aligned.m8n8.x4.shared.b16 {%0,%1,%2,%3}, [%4];" \
                 : "=r"(r0), "=r"(r1), "=r"(r2), "=r"(r3) : "r"(addr))

#define LDSM4T(r0, r1, r2, r3, addr) \
    asm volatile("ldmatrix.sync.aligned.m8n8.x4.trans.shared.b16 {%0,%1,%2,%3}, [%4];" \
                 : "=r"(r0), "=r"(r1), "=r"(r2), "=r"(r3) : "r"(addr))

#define MMA16816(d, a, b) \
    asm volatile("mma.sync.aligned.m16n8k16.row.col.f32.f16.f16.f32 " \
                 "{%0,%1,%2,%3}, {%4,%5,%6,%7}, {%8,%9}, {%0,%1,%2,%3};" \
                 : "+f"((d)[0]), "+f"((d)[1]), "+f"((d)[2]), "+f"((d)[3]) \
                 : "r"((a)[0]), "r"((a)[1]), "r"((a)[2]), "r"((a)[3]), \
                   "r"((b)[0]), "r"((b)[1]))

__device__ __forceinline__ void cpasync16(uint32_t daddr, const void* g) {
    asm volatile("cp.async.cg.shared.global [%0], [%1], 16;" :: "r"(daddr), "l"(g));
}

// ---------------- prep: weight transposes + X conversion, one launch --------
__global__ void __launch_bounds__(256)
prep_kernel(const float* __restrict__ x,
            const float* __restrict__ Wq, const float* __restrict__ Wo,
            const float* __restrict__ Wi, const float* __restrict__ W2,
            __half* __restrict__ X16,
            __half* __restrict__ oq, __half* __restrict__ oo,
            __half* __restrict__ oi, __half* __restrict__ o2)
{
    int b = blockIdx.x;
    if (b >= 768) {
        const int i = (b - 768) * 1024 + threadIdx.x * 4;
        float4 v = *(const float4*)(x + i);
        __half2 h0, h1;
        h0.x = __float2half_rn(v.x); h0.y = __float2half_rn(v.y);
        h1.x = __float2half_rn(v.z); h1.y = __float2half_rn(v.w);
        *(__half2*)(X16 + i)     = h0;
        *(__half2*)(X16 + i + 2) = h1;
        return;
    }
    __shared__ float t[32][33];
    const float* W; __half* o; int K, N;
    if (b < 192)      { W = Wq; o = oq; K = D;  N = D_QKV; }
    else if (b < 256) { W = Wo; o = oo; K = D;  N = D;     b -= 192; }
    else if (b < 512) { W = Wi; o = oi; K = D;  N = DI;    b -= 256; }
    else              { W = W2; o = o2; K = DI; N = D;     b -= 512; }
    const int nt = N / 32;
    const int n0 = (b % nt) * 32, k0 = (b / nt) * 32;
    const int tx = threadIdx.x & 31, ty = threadIdx.x >> 5;
    for (int i = ty; i < 32; i += 8)
        t[i][tx] = W[(size_t)(k0 + i) * N + n0 + tx];
    __syncthreads();
    for (int i = ty; i < 32; i += 8)
        o[(size_t)(n0 + i) * K + k0 + tx] = __float2half_rn(t[tx][i]);
}

// ---------------- fp16 mma.sync GEMM (128x128 tile, fp16 out) ---------------
#define TILE_B 16384
#define CH_B   (2 * TILE_B)
#define OFF_BW TILE_B
#define STAGES 3
#define GSMEM  (STAGES * CH_B)

__device__ __forceinline__ void load_chunk(const __half* __restrict__ A,
                                           const __half* __restrict__ B,
                                           int bm, int bn, int K, int k0,
                                           uint32_t sbuf, int tid)
{
#pragma unroll
    for (int t = 0; t < 4; t++) {
        const int u = tid + t * 256;
        const int row = u >> 3, c = u & 7;
        const uint32_t off = sw128(row * 128 + c * 16);
        cpasync16(sbuf + off,          A + (size_t)(bm + row) * K + k0 + c * 8);
        cpasync16(sbuf + OFF_BW + off, B + (size_t)(bn + row) * K + k0 + c * 8);
    }
}

// EPI: 0 none, 2 gelu. Output fp16 only.
template <int EPI>
__global__ void __launch_bounds__(256)
gemm_mma(const __half* __restrict__ A16, const __half* __restrict__ W,
         __half* __restrict__ C16, int N, int K)
{
    extern __shared__ char smem[];
    const uint32_t sb = smem_u32(smem);
    const int tid = threadIdx.x;
    const int wid = tid >> 5, lane = tid & 31;
    const int bm = blockIdx.y * 128, bn = blockIdx.x * 128;
    const int wm = (wid & 3) * 32;
    const int wn = (wid >> 2) * 64;
    const int nch = K >> 6;

    float acc[2][8][4];
#pragma unroll
    for (int mi = 0; mi < 2; mi++)
#pragma unroll
        for (int ni = 0; ni < 8; ni++)
#pragma unroll
            for (int j = 0; j < 4; j++) acc[mi][ni][j] = 0.f;

    load_chunk(A16, W, bm, bn, K, 0, sb, tid);
    asm volatile("cp.async.commit_group;" ::: "memory");
    if (nch > 1) load_chunk(A16, W, bm, bn, K, 64, sb + CH_B, tid);
    asm volatile("cp.async.commit_group;" ::: "memory");

    for (int c = 0; c < nch; c++) {
        asm volatile("cp.async.wait_group 1;" ::: "memory");
        __syncthreads();
        if (c + 2 < nch)
            load_chunk(A16, W, bm, bn, K, (c + 2) * 64, sb + ((c + 2) % STAGES) * CH_B, tid);
        asm volatile("cp.async.commit_group;" ::: "memory");

        const uint32_t st = sb + (c % STAGES) * CH_B;
#pragma unroll
        for (int ks = 0; ks < 4; ks++) {
            const uint32_t cofs = ks * 32 + (lane >> 4) * 16;
            uint32_t a[2][4];
#pragma unroll
            for (int mi = 0; mi < 2; mi++) {
                const uint32_t ro = sw128((wm + mi * 16 + (lane & 15)) * 128 + cofs);
                LDSM4(a[mi][0], a[mi][1], a[mi][2], a[mi][3], st + ro);
            }
            uint32_t b[8][2];
#pragma unroll
            for (int np = 0; np < 4; np++) {
                const uint32_t ro = sw128((wn + np * 16 + (lane & 15)) * 128 + cofs);
                uint32_t r0, r1, r2, r3;
                LDSM4(r0, r1, r2, r3, st + OFF_BW + ro);
                b[np * 2][0] = r0; b[np * 2][1] = r2;
                b[np * 2 + 1][0] = r1; b[np * 2 + 1][1] = r3;
            }
#pragma unroll
            for (int mi = 0; mi < 2; mi++)
#pragma unroll
                for (int ni = 0; ni < 8; ni++)
                    MMA16816(acc[mi][ni], a[mi], b[ni]);
        }
        __syncthreads();
    }

#pragma unroll
    for (int mi = 0; mi < 2; mi++) {
#pragma unroll
        for (int ni = 0; ni < 8; ni++) {
            const int row0 = bm + wm + mi * 16 + (lane >> 2);
            const int col  = bn + wn + ni * 8 + (lane & 3) * 2;
#pragma unroll
            for (int h = 0; h < 2; h++) {
                const size_t gofs = (size_t)(row0 + h * 8) * N + col;
                float vx = acc[mi][ni][h * 2 + 0];
                float vy = acc[mi][ni][h * 2 + 1];
                if (EPI == 2) {
                    vx = 0.5f * vx * (1.f + erff(vx * 0.70710678118654752f));
                    vy = 0.5f * vy * (1.f + erff(vy * 0.70710678118654752f));
                }
                __half2 hh;
                hh.x = __float2half_rn(vx);
                hh.y = __float2half_rn(vy);
                *(__half2*)(C16 + gofs) = hh;
            }
        }
    }
}

// ---------------- fused attention + att@Wo + residual + LN1 -----------------
// Grid 128 CTAs (1/SM). Each CTA: 4 groups = 128 rows.
// Wo resident in smem (loaded during attention phase). att staged in smem.
// smem layout: [Wo 131072][att 65536][Vs 20480][sp 2048]
#define AL_ATT  131072
#define AL_VS   (AL_ATT + 65536)       // 196608
#define AL_SP   (AL_VS + 20480)       // 217088
#define AL_SMEM (AL_SP + 2048)        // 219136

__global__ void __launch_bounds__(256, 1)
attn_ln1_kernel(const __half* __restrict__ qkv, const __half* __restrict__ W,
                const float* __restrict__ Rf,
                const float* __restrict__ g, const float* __restrict__ b,
                __half* __restrict__ Yh)
{
    extern __shared__ char smem[];
    const uint32_t sb = smem_u32(smem);
    const int tid = threadIdx.x;
    const int wid = tid >> 5, lane = tid & 31;
    const int qr = lane >> 2, qc = (lane & 3) * 2;
    const int bm = blockIdx.x * 128;

    // ---- kick off Wo load (4 chunk-tiles of [256 rows x 128B]) -------------
#pragma unroll
    for (int t = 0; t < 32; t++) {
        const int u = tid + t * 256;    // 0..8191 16B units
        const int chunk = u >> 11, within = u & 2047;
        const int row = within >> 3, c = within & 7;
        cpasync16(sb + chunk * 32768 + sw128(row * 128 + c * 16),
                  W + (size_t)row * 256 + chunk * 64 + c * 8);
    }
    asm volatile("cp.async.commit_group;" ::: "memory");

    // ---- phase 1: attention for 4 groups, O -> att smem (swizzled) ---------
    const uint32_t vsb = sb + AL_VS + wid * (32 * 40 * 2);
    for (int gidx = 0; gidx < 4; gidx++) {
        const int grp = blockIdx.x * 4 + gidx;
        const __half* base = qkv + (size_t)grp * GRP * D_QKV + wid * 96;

        __syncwarp();   // protect Vs from previous iteration's LDSM4T reads
        {
            const uint4* src = (const uint4*)(base + (size_t)lane * D_QKV + 64);
            uint4 v0 = src[0], v1 = src[1], v2 = src[2], v3 = src[3];
            uint32_t d = vsb + lane * 80;
            *(uint4*)(smem + (d - sb) + 0)  = v0;
            *(uint4*)(smem + (d - sb) + 16) = v1;
            *(uint4*)(smem + (d - sb) + 32) = v2;
            *(uint4*)(smem + (d - sb) + 48) = v3;
        }

        uint32_t a[2][2][4];
#pragma unroll
        for (int mi = 0; mi < 2; mi++) {
            const __half* plo = base + (size_t)(mi * 16 + qr) * D_QKV;
            const __half* phi = base + (size_t)(mi * 16 + qr + 8) * D_QKV;
#pragma unroll
            for (int kk = 0; kk < 2; kk++) {
                a[mi][kk][0] = *(const uint32_t*)(plo + kk * 16 + qc);
                a[mi][kk][1] = *(const uint32_t*)(phi + kk * 16 + qc);
                a[mi][kk][2] = *(const uint32_t*)(plo + kk * 16 + qc + 8);
                a[mi][kk][3] = *(const uint32_t*)(phi + kk * 16 + qc + 8);
            }
        }
        uint32_t bk[4][2][2];
#pragma unroll
        for (int ni = 0; ni < 4; ni++) {
            const __half* pn = base + (size_t)(ni * 8 + qr) * D_QKV + 32;
#pragma unroll
            for (int kk = 0; kk < 2; kk++) {
                bk[ni][kk][0] = *(const uint32_t*)(pn + kk * 16 + qc);
                bk[ni][kk][1] = *(const uint32_t*)(pn + kk * 16 + qc + 8);
            }
        }

        float s[2][4][4];
#pragma unroll
        for (int mi = 0; mi < 2; mi++)
#pragma unroll
            for (int ni = 0; ni < 4; ni++) {
#pragma unroll
                for (int j = 0; j < 4; j++) s[mi][ni][j] = 0.f;
#pragma unroll
                for (int kk = 0; kk < 2; kk++)
                    MMA16816(s[mi][ni], a[mi][kk], bk[ni][kk]);
            }

        const float scl = 0.17677669529663687f;
        uint32_t p[2][2][4];
        float inv_lo[2], inv_hi[2];
#pragma unroll
        for (int mi = 0; mi < 2; mi++) {
            float mlo = -1e30f, mhi = -1e30f;
#pragma unroll
            for (int ni = 0; ni < 4; ni++) {
#pragma unroll
                for (int j = 0; j < 4; j++) s[mi][ni][j] *= scl;
                mlo = fmaxf(mlo, fmaxf(s[mi][ni][0], s[mi][ni][1]));
                mhi = fmaxf(mhi, fmaxf(s[mi][ni][2], s[mi][ni][3]));
            }
#pragma unroll
            for (int o = 1; o < 4; o <<= 1) {
                mlo = fmaxf(mlo, __shfl_xor_sync(0xffffffffu, mlo, o));
                mhi = fmaxf(mhi, __shfl_xor_sync(0xffffffffu, mhi, o));
            }
            float slo = 0.f, shi = 0.f;
            float e[4][4];
#pragma unroll
            for (int ni = 0; ni < 4; ni++) {
                e[ni][0] = expf(s[mi][ni][0] - mlo);
                e[ni][1] = expf(s[mi][ni][1] - mlo);
                e[ni][2] = expf(s[mi][ni][2] - mhi);
                e[ni][3] = expf(s[mi][ni][3] - mhi);
                slo += e[ni][0] + e[ni][1];
                shi += e[ni][2] + e[ni][3];
            }
#pragma unroll
            for (int o = 1; o < 4; o <<= 1) {
                slo += __shfl_xor_sync(0xffffffffu, slo, o);
                shi += __shfl_xor_sync(0xffffffffu, shi, o);
            }
            inv_lo[mi] = 1.0f / slo;
            inv_hi[mi] = 1.0f / shi;
#pragma unroll
            for (int kk = 0; kk < 2; kk++) {
                __half2 h;
                h.x = __float2half_rn(e[2 * kk][0]);     h.y = __float2half_rn(e[2 * kk][1]);
                p[mi][kk][0] = *(uint32_t*)&h;
                h.x = __float2half_rn(e[2 * kk][2]);     h.y = __float2half_rn(e[2 * kk][3]);
                p[mi][kk][1] = *(uint32_t*)&h;
                h.x = __float2half_rn(e[2 * kk + 1][0]); h.y = __float2half_rn(e[2 * kk + 1][1]);
                p[mi][kk][2] = *(uint32_t*)&h;
                h.x = __float2half_rn(e[2 * kk + 1][2]); h.y = __float2half_rn(e[2 * kk + 1][3]);
                p[mi][kk][3] = *(uint32_t*)&h;
            }
        }

        __syncwarp();
        uint32_t bv[4][2][2];
#pragma unroll
        for (int kk = 0; kk < 2; kk++) {
#pragma unroll
            for (int ch = 0; ch < 2; ch++) {
                const int vrow = kk * 16 + ((lane >> 4) * 8) + (lane & 7);
                const int vcol = ch * 16 + ((lane >> 3) & 1) * 8;
                uint32_t r0, r1, r2, r3;
                LDSM4T(r0, r1, r2, r3, vsb + vrow * 80 + vcol * 2);
                bv[ch * 2][kk][0] = r0;     bv[ch * 2][kk][1] = r2;
                bv[ch * 2 + 1][kk][0] = r1; bv[ch * 2 + 1][kk][1] = r3;
            }
        }

        float o[2][4][4];
#pragma unroll
        for (int mi = 0; mi < 2; mi++)
#pragma unroll
            for (int n2 = 0; n2 < 4; n2++) {
#pragma unroll
                for (int j = 0; j < 4; j++) o[mi][n2][j] = 0.f;
#pragma unroll
                for (int kk = 0; kk < 2; kk++)
                    MMA16816(o[mi][n2], p[mi][kk], bv[n2][kk]);
            }

        // store O into swizzled att smem (chunk layout: [128 rows x 128B] x4)
#pragma unroll
        for (int mi = 0; mi < 2; mi++) {
#pragma unroll
            for (int n2 = 0; n2 < 4; n2++) {
                const int col = wid * HD + n2 * 8 + qc;
                const int chunk = col >> 6;
                const int within = (col & 63) * 2;
                const int rlo = gidx * 32 + mi * 16 + qr;
                __half2 h0, h1;
                h0.x = __float2half_rn(o[mi][n2][0] * inv_lo[mi]);
                h0.y = __float2half_rn(o[mi][n2][1] * inv_lo[mi]);
                h1.x = __float2half_rn(o[mi][n2][2] * inv_hi[mi]);
                h1.y = __float2half_rn(o[mi][n2][3] * inv_hi[mi]);
                *(__half2*)(smem + AL_ATT + chunk * 16384 + sw128(rlo * 128 + within)) = h0;
                *(__half2*)(smem + AL_ATT + chunk * 16384 + sw128((rlo + 8) * 128 + within)) = h1;
            }
        }
    }

    asm volatile("cp.async.wait_group 0;" ::: "memory");
    __syncthreads();

    // ---- phase 2: att@Wo + x + LN, 4 sub-tiles of 32 rows ------------------
    float* sp = (float*)(smem + AL_SP);   // [32 rows][8 warps][2]
    const int WN = wid * 32;

    for (int sub = 0; sub < 4; sub++) {
        float acc[2][4][4];
#pragma unroll
        for (int mi = 0; mi < 2; mi++)
#pragma unroll
            for (int ni = 0; ni < 4; ni++)
#pragma unroll
                for (int j = 0; j < 4; j++) acc[mi][ni][j] = 0.f;

#pragma unroll 4
        for (int ks = 0; ks < 16; ks++) {
            const uint32_t chb = (ks >> 2);
            const uint32_t cofs = (ks & 3) * 32 + (lane >> 4) * 16;
            uint32_t a[2][4];
#pragma unroll
            for (int mi = 0; mi < 2; mi++) {
                const uint32_t ro = AL_ATT + chb * 16384 +
                    sw128((sub * 32 + mi * 16 + (lane & 15)) * 128 + cofs);
                LDSM4(a[mi][0], a[mi][1], a[mi][2], a[mi][3], sb + ro);
            }
#pragma unroll
            for (int np = 0; np < 2; np++) {
                const uint32_t ro = chb * 32768 +
                    sw128((WN + np * 16 + (lane & 15)) * 128 + cofs);
                uint32_t r0, r1, r2, r3;
                LDSM4(r0, r1, r2, r3, sb + ro);
                uint32_t bb[2][2];
                bb[0][0] = r0; bb[0][1] = r2;
                bb[1][0] = r1; bb[1][1] = r3;
#pragma unroll
                for (int mi = 0; mi < 2; mi++)
#pragma unroll
                    for (int cc = 0; cc < 2; cc++)
                        MMA16816(acc[mi][np * 2 + cc], a[mi], bb[cc]);
            }
        }

        const int bmr = bm + sub * 32;
        // residual (fp32 x)
#pragma unroll
        for (int mi = 0; mi < 2; mi++)
#pragma unroll
            for (int h = 0; h < 2; h++) {
                const int row = mi * 16 + h * 8 + qr;
#pragma unroll
                for (int ni = 0; ni < 4; ni++) {
                    const int col = WN + ni * 8 + qc;
                    float2 f = *(const float2*)(Rf + (size_t)(bmr + row) * D + col);
                    acc[mi][ni][h * 2 + 0] += f.x;
                    acc[mi][ni][h * 2 + 1] += f.y;
                }
            }

        // LN partials
#pragma unroll
        for (int mi = 0; mi < 2; mi++)
#pragma unroll
            for (int h = 0; h < 2; h++) {
                float s1 = 0.f, s2 = 0.f;
#pragma unroll
                for (int ni = 0; ni < 4; ni++) {
                    float vx = acc[mi][ni][h * 2], vy = acc[mi][ni][h * 2 + 1];
                    s1 += vx + vy;
                    s2 += vx * vx + vy * vy;
                }
#pragma unroll
                for (int o = 1; o < 4; o <<= 1) {
                    s1 += __shfl_xor_sync(0xffffffffu, s1, o);
                    s2 += __shfl_xor_sync(0xffffffffu, s2, o);
                }
                if ((lane & 3) == 0) {
                    const int row = mi * 16 + h * 8 + qr;
                    sp[(row * 8 + wid) * 2 + 0] = s1;
                    sp[(row * 8 + wid) * 2 + 1] = s2;
                }
            }
        __syncthreads();

        // normalize + store
#pragma unroll
        for (int mi = 0; mi < 2; mi++)
#pragma unroll
            for (int h = 0; h < 2; h++) {
                const int row = mi * 16 + h * 8 + qr;
                float s1 = 0.f, s2 = 0.f;
#pragma unroll
                for (int q = 0; q < 8; q++) {
                    s1 += sp[(row * 8 + q) * 2 + 0];
                    s2 += sp[(row * 8 + q) * 2 + 1];
                }
                const float mean = s1 * (1.0f / D);
                const float var  = s2 * (1.0f / D) - mean * mean;
                const float rstd = rsqrtf(var + LN_EPS);
#pragma unroll
                for (int ni = 0; ni < 4; ni++) {
                    const int col = WN + ni * 8 + qc;
                    const float2 gg = *(const float2*)(g + col);
                    const float2 bb = *(const float2*)(b + col);
                    const float ox = (acc[mi][ni][h * 2]     - mean) * rstd * gg.x + bb.x;
                    const float oy = (acc[mi][ni][h * 2 + 1] - mean) * rstd * gg.y + bb.y;
                    __half2 hh;
                    hh.x = __float2half_rn(ox);
                    hh.y = __float2half_rn(oy);
                    *(__half2*)(Yh + (size_t)(bmr + row) * D + col) = hh;
                }
            }
        __syncthreads();
    }
}

// ---------------- LN2: fused GEMM + residual + LayerNorm, 64x256, K=1024 ----
#define LN_ATILE 8192
#define LN_CH (LN_ATILE + 32768)
#define LN_SMEM (2 * LN_CH + 64 * 4 * 2 * 4)

__device__ __forceinline__ void load_chunk_ln2(const __half* __restrict__ A,
                                               const __half* __restrict__ W,
                                               int bm, int K, int k0,
                                               uint32_t sbuf, int tid)
{
#pragma unroll
    for (int t = 0; t < 2; t++) {
        const int u = tid + t * 256;
        const int row = u >> 3, c = u & 7;
        cpasync16(sbuf + sw128(row * 128 + c * 16),
                  A + (size_t)(bm + row) * K + k0 + c * 8);
    }
#pragma unroll
    for (int t = 0; t < 8; t++) {
        const int u = tid + t * 256;
        const int row = u >> 3, c = u & 7;
        cpasync16(sbuf + LN_ATILE + sw128(row * 128 + c * 16),
                  W + (size_t)(row) * K + k0 + c * 8);
    }
}

__global__ void __launch_bounds__(256, 2)
ln2_kernel(const __half* __restrict__ A16, const __half* __restrict__ W,
           const __half* __restrict__ Rh,
           const float* __restrict__ g, const float* __restrict__ b,
           float* __restrict__ Y, int K)
{
    extern __shared__ char smem[];
    const uint32_t sb = smem_u32(smem);
    const int tid = threadIdx.x;
    const int wid = tid >> 5, lane = tid & 31;
    const int bm = blockIdx.x * 64;
    const int WM = (wid & 1) * 32;
    const int WN = (wid >> 1) * 64;
    const int wq = wid >> 1;
    const int nch = K >> 6;

    float acc[2][8][4];
#pragma unroll
    for (int mi = 0; mi < 2; mi++)
#pragma unroll
        for (int ni = 0; ni < 8; ni++)
#pragma unroll
            for (int j = 0; j < 4; j++) acc[mi][ni][j] = 0.f;

    load_chunk_ln2(A16, W, bm, K, 0, sb, tid);
    asm volatile("cp.async.commit_group;" ::: "memory");

    for (int c = 0; c < nch; c++) {
        if (c + 1 < nch) {
            load_chunk_ln2(A16, W, bm, K, (c + 1) * 64, sb + ((c + 1) & 1) * LN_CH, tid);
            asm volatile("cp.async.commit_group;" ::: "memory");
            asm volatile("cp.async.wait_group 1;" ::: "memory");
        } else {
            asm volatile("cp.async.wait_group 0;" ::: "memory");
        }
        __syncthreads();

        const uint32_t st = sb + (c & 1) * LN_CH;
#pragma unroll
        for (int ks = 0; ks < 4; ks++) {
            const uint32_t cofs = ks * 32 + (lane >> 4) * 16;
            uint32_t a[2][4];
#pragma unroll
            for (int mi = 0; mi < 2; mi++) {
                const uint32_t ro = sw128((WM + mi * 16 + (lane & 15)) * 128 + cofs);
                LDSM4(a[mi][0], a[mi][1], a[mi][2], a[mi][3], st + ro);
            }
#pragma unroll
            for (int np = 0; np < 4; np++) {
                const uint32_t ro = sw128((WN + np * 16 + (lane & 15)) * 128 + cofs);
                uint32_t r0, r1, r2, r3;
                LDSM4(r0, r1, r2, r3, st + LN_ATILE + ro);
                uint32_t bb[2][2];
                bb[0][0] = r0; bb[0][1] = r2;
                bb[1][0] = r1; bb[1][1] = r3;
#pragma unroll
                for (int mi = 0; mi < 2; mi++)
#pragma unroll
                    for (int cc = 0; cc < 2; cc++)
                        MMA16816(acc[mi][np * 2 + cc], a[mi], bb[cc]);
            }
        }
        __syncthreads();
    }

#pragma unroll
    for (int mi = 0; mi < 2; mi++)
#pragma unroll
        for (int h = 0; h < 2; h++) {
            const int row = WM + mi * 16 + h * 8 + (lane >> 2);
#pragma unroll
            for (int ni = 0; ni < 8; ni++) {
                const int col = WN + ni * 8 + (lane & 3) * 2;
                float2 f = __half22float2(*(const __half2*)(Rh + (size_t)(bm + row) * D + col));
                acc[mi][ni][h * 2 + 0] += f.x;
                acc[mi][ni][h * 2 + 1] += f.y;
            }
        }

    float* sp = (float*)(smem + 2 * LN_CH);
#pragma unroll
    for (int mi = 0; mi < 2; mi++)
#pragma unroll
        for (int h = 0; h < 2; h++) {
            float s1 = 0.f, s2 = 0.f;
#pragma unroll
            for (int ni = 0; ni < 8; ni++) {
                float vx = acc[mi][ni][h * 2], vy = acc[mi][ni][h * 2 + 1];
                s1 += vx + vy;
                s2 += vx * vx + vy * vy;
            }
#pragma unroll
            for (int o = 1; o < 4; o <<= 1) {
                s1 += __shfl_xor_sync(0xffffffffu, s1, o);
                s2 += __shfl_xor_sync(0xffffffffu, s2, o);
            }
            if ((lane & 3) == 0) {
                const int row = WM + mi * 16 + h * 8 + (lane >> 2);
                sp[(row * 4 + wq) * 2 + 0] = s1;
                sp[(row * 4 + wq) * 2 + 1] = s2;
            }
        }
    __syncthreads();

#pragma unroll
    for (int mi = 0; mi < 2; mi++)
#pragma unroll
        for (int h = 0; h < 2; h++) {
            const int row = WM + mi * 16 + h * 8 + (lane >> 2);
            float s1 = 0.f, s2 = 0.f;
#pragma unroll
            for (int q = 0; q < 4; q++) {
                s1 += sp[(row * 4 + q) * 2 + 0];
                s2 += sp[(row * 4 + q) * 2 + 1];
            }
            const float mean = s1 * (1.0f / D);
            const float var  = s2 * (1.0f / D) - mean * mean;
            const float rstd = rsqrtf(var + LN_EPS);
#pragma unroll
            for (int ni = 0; ni < 8; ni++) {
                const int col = WN + ni * 8 + (lane & 3) * 2;
                const float2 gg = *(const float2*)(g + col);
                const float2 bb = *(const float2*)(b + col);
                float2 f;
                f.x = (acc[mi][ni][h * 2]     - mean) * rstd * gg.x + bb.x;
                f.y = (acc[mi][ni][h * 2 + 1] - mean) * rstd * gg.y + bb.y;
                *(float2*)(Y + (size_t)(bm + row) * D + col) = f;
            }
        }
}

// ---------------- launch ----------------------------------------------------
extern "C" void kernel_launch(void* const* d_in, const int* in_sizes, int n_in,
                              void* d_out, int out_size)
{
    const float* x      = (const float*)d_in[0];
    const float* W_qkv  = (const float*)d_in[2];
    const float* W_o    = (const float*)d_in[3];
    const float* ln1_g  = (const float*)d_in[4];
    const float* ln1_b  = (const float*)d_in[5];
    const float* W_i    = (const float*)d_in[6];
    const float* W_out2 = (const float*)d_in[7];
    const float* ln2_g  = (const float*)d_in[8];
    const float* ln2_b  = (const float*)d_in[9];
    float* out = (float*)d_out;

    __half *X16, *qkv16, *pre16, *inter16;
    __half *Wq16, *Wo16, *Wi16, *W216;
    cudaGetSymbolAddress((void**)&X16, g_X16);
    cudaGetSymbolAddress((void**)&qkv16, g_qkv16);
    cudaGetSymbolAddress((void**)&pre16, g_pre16);
    cudaGetSymbolAddress((void**)&inter16, g_inter16);
    cudaGetSymbolAddress((void**)&Wq16, g_Wqkv16);
    cudaGetSymbolAddress((void**)&Wo16, g_Wo16);
    cudaGetSymbolAddress((void**)&Wi16, g_Wi16);
    cudaGetSymbolAddress((void**)&W216, g_W216);

    cudaFuncSetAttribute(gemm_mma<0>, cudaFuncAttributeMaxDynamicSharedMemorySize, GSMEM);
    cudaFuncSetAttribute(gemm_mma<2>, cudaFuncAttributeMaxDynamicSharedMemorySize, GSMEM);
    cudaFuncSetAttribute(attn_ln1_kernel, cudaFuncAttributeMaxDynamicSharedMemorySize, AL_SMEM);
    cudaFuncSetAttribute(ln2_kernel, cudaFuncAttributeMaxDynamicSharedMemorySize, LN_SMEM);

    // 0) prep: weight transposes + X conversion (one launch)
    prep_kernel<<<768 + NV * D / 1024, 256>>>(x, W_qkv, W_o, W_i, W_out2,
                                              X16, Wq16, Wo16, Wi16, W216);

    // 1) qkv16 = X @ W_qkv        [16384, 768] fp16
    gemm_mma<0><<<dim3(D_QKV / 128, NV / 128), 256, GSMEM>>>(X16, Wq16, qkv16, D_QKV, D);
    // 2+3+4) pre16 = LN1(attn(qkv) @ W_o + X)   [fused, W-resident]
    attn_ln1_kernel<<<128, 256, AL_SMEM>>>(qkv16, Wo16, x, ln1_g, ln1_b, pre16);
    // 5) inter16 = gelu(pre @ W_i)
    gemm_mma<2><<<dim3(DI / 128, NV / 128), 256, GSMEM>>>(pre16, Wi16, inter16, DI, D);
    // 6+7) out = LN2(inter @ W_out2 + pre16)
    ln2_kernel<<<NV / 64, 256, LN_SMEM>>>(inter16, W216, pre16, ln2_g, ln2_b, out, DI);
}

// round 15
// speedup vs baseline: 1.1641x; 1.0521x over previous
#include <cuda_runtime.h>
#include <cuda_fp16.h>
#include <math.h>
#include <stdint.h>

// Problem constants (fixed by setup_inputs)
#define NV 16384
#define GRP 32
#define NGROUPS 512
#define D 256
#define NH 8
#define HD 32
#define DI 1024
#define D_QKV 768
#define LN_EPS 1e-12f

// ---------------- scratch (device globals; no allocation allowed) ----------
__device__ __half g_X16[NV * D];
__device__ __half g_qkv16[NV * D_QKV];
__device__ __half g_pre16[NV * D];
__device__ __half g_inter16[NV * DI];
__device__ __half g_Wqkv16[D_QKV * D];
__device__ __half g_Wo16[D * D];
__device__ __half g_Wi16[DI * D];
__device__ __half g_W216[D * DI];

// ---------------- helpers ---------------------------------------------------
__device__ __forceinline__ uint32_t smem_u32(const void* p) {
    uint32_t a;
    asm("{ .reg .u64 t; cvta.to.shared.u64 t, %1; cvt.u32.u64 %0, t; }" : "=r"(a) : "l"(p));
    return a;
}
__device__ __forceinline__ uint32_t sw128(uint32_t x) { return x ^ ((x >> 3) & 0x70); }

#define LDSM4(r0, r1, r2, r3, addr) \
    asm volatile("ldmatrix.sync.aligned.m8n8.x4.shared.b16 {%0,%1,%2,%3}, [%4];" \
                 : "=r"(r0), "=r"(r1), "=r"(r2), "=r"(r3) : "r"(addr))

#define LDSM4T(r0, r1, r2, r3, addr) \
    asm volatile("ldmatrix.sync.aligned.m8n8.x4.trans.shared.b16 {%0,%1,%2,%3}, [%4];" \
                 : "=r"(r0), "=r"(r1), "=r"(r2), "=r"(r3) : "r"(addr))

#define MMA16816(d, a, b) \
    asm volatile("mma.sync.aligned.m16n8k16.row.col.f32.f16.f16.f32 " \
                 "{%0,%1,%2,%3}, {%4,%5,%6,%7}, {%8,%9}, {%0,%1,%2,%3};" \
                 : "+f"((d)[0]), "+f"((d)[1]), "+f"((d)[2]), "+f"((d)[3]) \
                 : "r"((a)[0]), "r"((a)[1]), "r"((a)[2]), "r"((a)[3]), \
                   "r"((b)[0]), "r"((b)[1]))

__device__ __forceinline__ void cpasync16(uint32_t daddr, const void* g) {
    asm volatile("cp.async.cg.shared.global [%0], [%1], 16;" :: "r"(daddr), "l"(g));
}

// ---------------- prep: weight transposes + X conversion, one launch --------
__global__ void __launch_bounds__(256)
prep_kernel(const float* __restrict__ x,
            const float* __restrict__ Wq, const float* __restrict__ Wo,
            const float* __restrict__ Wi, const float* __restrict__ W2,
            __half* __restrict__ X16,
            __half* __restrict__ oq, __half* __restrict__ oo,
            __half* __restrict__ oi, __half* __restrict__ o2)
{
    int b = blockIdx.x;
    if (b >= 768) {
        const int i = (b - 768) * 1024 + threadIdx.x * 4;
        float4 v = *(const float4*)(x + i);
        __half2 h0, h1;
        h0.x = __float2half_rn(v.x); h0.y = __float2half_rn(v.y);
        h1.x = __float2half_rn(v.z); h1.y = __float2half_rn(v.w);
        *(__half2*)(X16 + i)     = h0;
        *(__half2*)(X16 + i + 2) = h1;
        return;
    }
    __shared__ float t[32][33];
    const float* W; __half* o; int K, N;
    if (b < 192)      { W = Wq; o = oq; K = D;  N = D_QKV; }
    else if (b < 256) { W = Wo; o = oo; K = D;  N = D;     b -= 192; }
    else if (b < 512) { W = Wi; o = oi; K = D;  N = DI;    b -= 256; }
    else              { W = W2; o = o2; K = DI; N = D;     b -= 512; }
    const int nt = N / 32;
    const int n0 = (b % nt) * 32, k0 = (b / nt) * 32;
    const int tx = threadIdx.x & 31, ty = threadIdx.x >> 5;
    for (int i = ty; i < 32; i += 8)
        t[i][tx] = W[(size_t)(k0 + i) * N + n0 + tx];
    __syncthreads();
    for (int i = ty; i < 32; i += 8)
        o[(size_t)(n0 + i) * K + k0 + tx] = __float2half_rn(t[tx][i]);
}

// ---------------- fp16 mma.sync GEMM (128x128 tile, fp16 out) ---------------
#define TILE_B 16384
#define CH_B   (2 * TILE_B)
#define OFF_BW TILE_B
#define STAGES 3
#define GSMEM  (STAGES * CH_B)

__device__ __forceinline__ void load_chunk(const __half* __restrict__ A,
                                           const __half* __restrict__ B,
                                           int bm, int bn, int K, int k0,
                                           uint32_t sbuf, int tid)
{
#pragma unroll
    for (int t = 0; t < 4; t++) {
        const int u = tid + t * 256;
        const int row = u >> 3, c = u & 7;
        const uint32_t off = sw128(row * 128 + c * 16);
        cpasync16(sbuf + off,          A + (size_t)(bm + row) * K + k0 + c * 8);
        cpasync16(sbuf + OFF_BW + off, B + (size_t)(bn + row) * K + k0 + c * 8);
    }
}

// EPI: 0 none, 2 gelu (staged epilogue). Output fp16 only.
template <int EPI>
__global__ void __launch_bounds__(256, 2)
gemm_mma(const __half* __restrict__ A16, const __half* __restrict__ W,
         __half* __restrict__ C16, int N, int K)
{
    extern __shared__ char smem[];
    const uint32_t sb = smem_u32(smem);
    const int tid = threadIdx.x;
    const int wid = tid >> 5, lane = tid & 31;
    const int bm = blockIdx.y * 128, bn = blockIdx.x * 128;
    const int wm = (wid & 3) * 32;
    const int wn = (wid >> 2) * 64;
    const int nch = K >> 6;

    float acc[2][8][4];
#pragma unroll
    for (int mi = 0; mi < 2; mi++)
#pragma unroll
        for (int ni = 0; ni < 8; ni++)
#pragma unroll
            for (int j = 0; j < 4; j++) acc[mi][ni][j] = 0.f;

    load_chunk(A16, W, bm, bn, K, 0, sb, tid);
    asm volatile("cp.async.commit_group;" ::: "memory");
    if (nch > 1) load_chunk(A16, W, bm, bn, K, 64, sb + CH_B, tid);
    asm volatile("cp.async.commit_group;" ::: "memory");

    for (int c = 0; c < nch; c++) {
        asm volatile("cp.async.wait_group 1;" ::: "memory");
        __syncthreads();
        if (c + 2 < nch)
            load_chunk(A16, W, bm, bn, K, (c + 2) * 64, sb + ((c + 2) % STAGES) * CH_B, tid);
        asm volatile("cp.async.commit_group;" ::: "memory");

        const uint32_t st = sb + (c % STAGES) * CH_B;
#pragma unroll
        for (int ks = 0; ks < 4; ks++) {
            const uint32_t cofs = ks * 32 + (lane >> 4) * 16;
            uint32_t a[2][4];
#pragma unroll
            for (int mi = 0; mi < 2; mi++) {
                const uint32_t ro = sw128((wm + mi * 16 + (lane & 15)) * 128 + cofs);
                LDSM4(a[mi][0], a[mi][1], a[mi][2], a[mi][3], st + ro);
            }
            uint32_t b[8][2];
#pragma unroll
            for (int np = 0; np < 4; np++) {
                const uint32_t ro = sw128((wn + np * 16 + (lane & 15)) * 128 + cofs);
                uint32_t r0, r1, r2, r3;
                LDSM4(r0, r1, r2, r3, st + OFF_BW + ro);
                b[np * 2][0] = r0; b[np * 2][1] = r2;
                b[np * 2 + 1][0] = r1; b[np * 2 + 1][1] = r3;
            }
#pragma unroll
            for (int mi = 0; mi < 2; mi++)
#pragma unroll
                for (int ni = 0; ni < 8; ni++)
                    MMA16816(acc[mi][ni], a[mi], b[ni]);
        }
        __syncthreads();
    }

    if (EPI == 0) {
        // direct fp16 epilogue
#pragma unroll
        for (int mi = 0; mi < 2; mi++) {
#pragma unroll
            for (int ni = 0; ni < 8; ni++) {
                const int row0 = bm + wm + mi * 16 + (lane >> 2);
                const int col  = bn + wn + ni * 8 + (lane & 3) * 2;
#pragma unroll
                for (int h = 0; h < 2; h++) {
                    const size_t gofs = (size_t)(row0 + h * 8) * N + col;
                    __half2 hh;
                    hh.x = __float2half_rn(acc[mi][ni][h * 2 + 0]);
                    hh.y = __float2half_rn(acc[mi][ni][h * 2 + 1]);
                    *(__half2*)(C16 + gofs) = hh;
                }
            }
        }
    } else {
        // staged gelu epilogue: acc -> smem fp32 -> linear gelu+store
        float* stg = (float*)smem;   // 128x128 fp32 = 64KB
#pragma unroll
        for (int mi = 0; mi < 2; mi++) {
#pragma unroll
            for (int ni = 0; ni < 8; ni++) {
                const int r0 = wm + mi * 16 + (lane >> 2);
                const int col = wn + ni * 8 + (lane & 3) * 2;
#pragma unroll
                for (int h = 0; h < 2; h++) {
                    stg[(r0 + h * 8) * 128 + col]     = acc[mi][ni][h * 2 + 0];
                    stg[(r0 + h * 8) * 128 + col + 1] = acc[mi][ni][h * 2 + 1];
                }
            }
        }
        __syncthreads();
#pragma unroll
        for (int t = 0; t < 16; t++) {
            const int u = tid + t * 256;       // 0..4095 float4 units
            const int row = u >> 5, c4 = u & 31;
            float4 v = ((const float4*)stg)[u];
            v.x = 0.5f * v.x * (1.f + erff(v.x * 0.70710678118654752f));
            v.y = 0.5f * v.y * (1.f + erff(v.y * 0.70710678118654752f));
            v.z = 0.5f * v.z * (1.f + erff(v.z * 0.70710678118654752f));
            v.w = 0.5f * v.w * (1.f + erff(v.w * 0.70710678118654752f));
            __half2 h0, h1;
            h0.x = __float2half_rn(v.x); h0.y = __float2half_rn(v.y);
            h1.x = __float2half_rn(v.z); h1.y = __float2half_rn(v.w);
            const size_t gofs = (size_t)(bm + row) * N + bn + c4 * 4;
            *(__half2*)(C16 + gofs)     = h0;
            *(__half2*)(C16 + gofs + 2) = h1;
        }
    }
}

// ---------------- fused attention + att@Wo + residual + LN1 -----------------
#define AL_ATT  131072
#define AL_VS   (AL_ATT + 65536)
#define AL_SP   (AL_VS + 20480)
#define AL_SMEM (AL_SP + 2048)

__global__ void __launch_bounds__(256, 1)
attn_ln1_kernel(const __half* __restrict__ qkv, const __half* __restrict__ W,
                const float* __restrict__ Rf,
                const float* __restrict__ g, const float* __restrict__ b,
                __half* __restrict__ Yh)
{
    extern __shared__ char smem[];
    const uint32_t sb = smem_u32(smem);
    const int tid = threadIdx.x;
    const int wid = tid >> 5, lane = tid & 31;
    const int qr = lane >> 2, qc = (lane & 3) * 2;
    const int bm = blockIdx.x * 128;

#pragma unroll
    for (int t = 0; t < 32; t++) {
        const int u = tid + t * 256;
        const int chunk = u >> 11, within = u & 2047;
        const int row = within >> 3, c = within & 7;
        cpasync16(sb + chunk * 32768 + sw128(row * 128 + c * 16),
                  W + (size_t)row * 256 + chunk * 64 + c * 8);
    }
    asm volatile("cp.async.commit_group;" ::: "memory");

    const uint32_t vsb = sb + AL_VS + wid * (32 * 40 * 2);
    for (int gidx = 0; gidx < 4; gidx++) {
        const int grp = blockIdx.x * 4 + gidx;
        const __half* base = qkv + (size_t)grp * GRP * D_QKV + wid * 96;

        __syncwarp();
        {
            const uint4* src = (const uint4*)(base + (size_t)lane * D_QKV + 64);
            uint4 v0 = src[0], v1 = src[1], v2 = src[2], v3 = src[3];
            uint32_t d = vsb + lane * 80;
            *(uint4*)(smem + (d - sb) + 0)  = v0;
            *(uint4*)(smem + (d - sb) + 16) = v1;
            *(uint4*)(smem + (d - sb) + 32) = v2;
            *(uint4*)(smem + (d - sb) + 48) = v3;
        }

        uint32_t a[2][2][4];
#pragma unroll
        for (int mi = 0; mi < 2; mi++) {
            const __half* plo = base + (size_t)(mi * 16 + qr) * D_QKV;
            const __half* phi = base + (size_t)(mi * 16 + qr + 8) * D_QKV;
#pragma unroll
            for (int kk = 0; kk < 2; kk++) {
                a[mi][kk][0] = *(const uint32_t*)(plo + kk * 16 + qc);
                a[mi][kk][1] = *(const uint32_t*)(phi + kk * 16 + qc);
                a[mi][kk][2] = *(const uint32_t*)(plo + kk * 16 + qc + 8);
                a[mi][kk][3] = *(const uint32_t*)(phi + kk * 16 + qc + 8);
            }
        }
        uint32_t bk[4][2][2];
#pragma unroll
        for (int ni = 0; ni < 4; ni++) {
            const __half* pn = base + (size_t)(ni * 8 + qr) * D_QKV + 32;
#pragma unroll
            for (int kk = 0; kk < 2; kk++) {
                bk[ni][kk][0] = *(const uint32_t*)(pn + kk * 16 + qc);
                bk[ni][kk][1] = *(const uint32_t*)(pn + kk * 16 + qc + 8);
            }
        }

        float s[2][4][4];
#pragma unroll
        for (int mi = 0; mi < 2; mi++)
#pragma unroll
            for (int ni = 0; ni < 4; ni++) {
#pragma unroll
                for (int j = 0; j < 4; j++) s[mi][ni][j] = 0.f;
#pragma unroll
                for (int kk = 0; kk < 2; kk++)
                    MMA16816(s[mi][ni], a[mi][kk], bk[ni][kk]);
            }

        const float scl = 0.17677669529663687f;
        uint32_t p[2][2][4];
        float inv_lo[2], inv_hi[2];
#pragma unroll
        for (int mi = 0; mi < 2; mi++) {
            float mlo = -1e30f, mhi = -1e30f;
#pragma unroll
            for (int ni = 0; ni < 4; ni++) {
#pragma unroll
                for (int j = 0; j < 4; j++) s[mi][ni][j] *= scl;
                mlo = fmaxf(mlo, fmaxf(s[mi][ni][0], s[mi][ni][1]));
                mhi = fmaxf(mhi, fmaxf(s[mi][ni][2], s[mi][ni][3]));
            }
#pragma unroll
            for (int o = 1; o < 4; o <<= 1) {
                mlo = fmaxf(mlo, __shfl_xor_sync(0xffffffffu, mlo, o));
                mhi = fmaxf(mhi, __shfl_xor_sync(0xffffffffu, mhi, o));
            }
            float slo = 0.f, shi = 0.f;
            float e[4][4];
#pragma unroll
            for (int ni = 0; ni < 4; ni++) {
                e[ni][0] = expf(s[mi][ni][0] - mlo);
                e[ni][1] = expf(s[mi][ni][1] - mlo);
                e[ni][2] = expf(s[mi][ni][2] - mhi);
                e[ni][3] = expf(s[mi][ni][3] - mhi);
                slo += e[ni][0] + e[ni][1];
                shi += e[ni][2] + e[ni][3];
            }
#pragma unroll
            for (int o = 1; o < 4; o <<= 1) {
                slo += __shfl_xor_sync(0xffffffffu, slo, o);
                shi += __shfl_xor_sync(0xffffffffu, shi, o);
            }
            inv_lo[mi] = 1.0f / slo;
            inv_hi[mi] = 1.0f / shi;
#pragma unroll
            for (int kk = 0; kk < 2; kk++) {
                __half2 h;
                h.x = __float2half_rn(e[2 * kk][0]);     h.y = __float2half_rn(e[2 * kk][1]);
                p[mi][kk][0] = *(uint32_t*)&h;
                h.x = __float2half_rn(e[2 * kk][2]);     h.y = __float2half_rn(e[2 * kk][3]);
                p[mi][kk][1] = *(uint32_t*)&h;
                h.x = __float2half_rn(e[2 * kk + 1][0]); h.y = __float2half_rn(e[2 * kk + 1][1]);
                p[mi][kk][2] = *(uint32_t*)&h;
                h.x = __float2half_rn(e[2 * kk + 1][2]); h.y = __float2half_rn(e[2 * kk + 1][3]);
                p[mi][kk][3] = *(uint32_t*)&h;
            }
        }

        __syncwarp();
        uint32_t bv[4][2][2];
#pragma unroll
        for (int kk = 0; kk < 2; kk++) {
#pragma unroll
            for (int ch = 0; ch < 2; ch++) {
                const int vrow = kk * 16 + ((lane >> 4) * 8) + (lane & 7);
                const int vcol = ch * 16 + ((lane >> 3) & 1) * 8;
                uint32_t r0, r1, r2, r3;
                LDSM4T(r0, r1, r2, r3, vsb + vrow * 80 + vcol * 2);
                bv[ch * 2][kk][0] = r0;     bv[ch * 2][kk][1] = r2;
                bv[ch * 2 + 1][kk][0] = r1; bv[ch * 2 + 1][kk][1] = r3;
            }
        }

        float o[2][4][4];
#pragma unroll
        for (int mi = 0; mi < 2; mi++)
#pragma unroll
            for (int n2 = 0; n2 < 4; n2++) {
#pragma unroll
                for (int j = 0; j < 4; j++) o[mi][n2][j] = 0.f;
#pragma unroll
                for (int kk = 0; kk < 2; kk++)
                    MMA16816(o[mi][n2], p[mi][kk], bv[n2][kk]);
            }

#pragma unroll
        for (int mi = 0; mi < 2; mi++) {
#pragma unroll
            for (int n2 = 0; n2 < 4; n2++) {
                const int col = wid * HD + n2 * 8 + qc;
                const int chunk = col >> 6;
                const int within = (col & 63) * 2;
                const int rlo = gidx * 32 + mi * 16 + qr;
                __half2 h0, h1;
                h0.x = __float2half_rn(o[mi][n2][0] * inv_lo[mi]);
                h0.y = __float2half_rn(o[mi][n2][1] * inv_lo[mi]);
                h1.x = __float2half_rn(o[mi][n2][2] * inv_hi[mi]);
                h1.y = __float2half_rn(o[mi][n2][3] * inv_hi[mi]);
                *(__half2*)(smem + AL_ATT + chunk * 16384 + sw128(rlo * 128 + within)) = h0;
                *(__half2*)(smem + AL_ATT + chunk * 16384 + sw128((rlo + 8) * 128 + within)) = h1;
            }
        }
    }

    asm volatile("cp.async.wait_group 0;" ::: "memory");
    __syncthreads();

    float* sp = (float*)(smem + AL_SP);
    const int WN = wid * 32;

    for (int sub = 0; sub < 4; sub++) {
        float acc[2][4][4];
#pragma unroll
        for (int mi = 0; mi < 2; mi++)
#pragma unroll
            for (int ni = 0; ni < 4; ni++)
#pragma unroll
                for (int j = 0; j < 4; j++) acc[mi][ni][j] = 0.f;

#pragma unroll 4
        for (int ks = 0; ks < 16; ks++) {
            const uint32_t chb = (ks >> 2);
            const uint32_t cofs = (ks & 3) * 32 + (lane >> 4) * 16;
            uint32_t a[2][4];
#pragma unroll
            for (int mi = 0; mi < 2; mi++) {
                const uint32_t ro = AL_ATT + chb * 16384 +
                    sw128((sub * 32 + mi * 16 + (lane & 15)) * 128 + cofs);
                LDSM4(a[mi][0], a[mi][1], a[mi][2], a[mi][3], sb + ro);
            }
#pragma unroll
            for (int np = 0; np < 2; np++) {
                const uint32_t ro = chb * 32768 +
                    sw128((WN + np * 16 + (lane & 15)) * 128 + cofs);
                uint32_t r0, r1, r2, r3;
                LDSM4(r0, r1, r2, r3, sb + ro);
                uint32_t bb[2][2];
                bb[0][0] = r0; bb[0][1] = r2;
                bb[1][0] = r1; bb[1][1] = r3;
#pragma unroll
                for (int mi = 0; mi < 2; mi++)
#pragma unroll
                    for (int cc = 0; cc < 2; cc++)
                        MMA16816(acc[mi][np * 2 + cc], a[mi], bb[cc]);
            }
        }

        const int bmr = bm + sub * 32;
#pragma unroll
        for (int mi = 0; mi < 2; mi++)
#pragma unroll
            for (int h = 0; h < 2; h++) {
                const int row = mi * 16 + h * 8 + qr;
#pragma unroll
                for (int ni = 0; ni < 4; ni++) {
                    const int col = WN + ni * 8 + qc;
                    float2 f = *(const float2*)(Rf + (size_t)(bmr + row) * D + col);
                    acc[mi][ni][h * 2 + 0] += f.x;
                    acc[mi][ni][h * 2 + 1] += f.y;
                }
            }

#pragma unroll
        for (int mi = 0; mi < 2; mi++)
#pragma unroll
            for (int h = 0; h < 2; h++) {
                float s1 = 0.f, s2 = 0.f;
#pragma unroll
                for (int ni = 0; ni < 4; ni++) {
                    float vx = acc[mi][ni][h * 2], vy = acc[mi][ni][h * 2 + 1];
                    s1 += vx + vy;
                    s2 += vx * vx + vy * vy;
                }
#pragma unroll
                for (int o = 1; o < 4; o <<= 1) {
                    s1 += __shfl_xor_sync(0xffffffffu, s1, o);
                    s2 += __shfl_xor_sync(0xffffffffu, s2, o);
                }
                if ((lane & 3) == 0) {
                    const int row = mi * 16 + h * 8 + qr;
                    sp[(row * 8 + wid) * 2 + 0] = s1;
                    sp[(row * 8 + wid) * 2 + 1] = s2;
                }
            }
        __syncthreads();

#pragma unroll
        for (int mi = 0; mi < 2; mi++)
#pragma unroll
            for (int h = 0; h < 2; h++) {
                const int row = mi * 16 + h * 8 + qr;
                float s1 = 0.f, s2 = 0.f;
#pragma unroll
                for (int q = 0; q < 8; q++) {
                    s1 += sp[(row * 8 + q) * 2 + 0];
                    s2 += sp[(row * 8 + q) * 2 + 1];
                }
                const float mean = s1 * (1.0f / D);
                const float var  = s2 * (1.0f / D) - mean * mean;
                const float rstd = rsqrtf(var + LN_EPS);
#pragma unroll
                for (int ni = 0; ni < 4; ni++) {
                    const int col = WN + ni * 8 + qc;
                    const float2 gg = *(const float2*)(g + col);
                    const float2 bb = *(const float2*)(b + col);
                    const float ox = (acc[mi][ni][h * 2]     - mean) * rstd * gg.x + bb.x;
                    const float oy = (acc[mi][ni][h * 2 + 1] - mean) * rstd * gg.y + bb.y;
                    __half2 hh;
                    hh.x = __float2half_rn(ox);
                    hh.y = __float2half_rn(oy);
                    *(__half2*)(Yh + (size_t)(bmr + row) * D + col) = hh;
                }
            }
        __syncthreads();
    }
}

// ---------------- LN2: fused GEMM + residual + LayerNorm, 64x256, K=1024 ----
#define LN_ATILE 8192
#define LN_CH (LN_ATILE + 32768)
#define LN_SMEM (2 * LN_CH + 64 * 4 * 2 * 4)

__device__ __forceinline__ void load_chunk_ln2(const __half* __restrict__ A,
                                               const __half* __restrict__ W,
                                               int bm, int K, int k0,
                                               uint32_t sbuf, int tid)
{
#pragma unroll
    for (int t = 0; t < 2; t++) {
        const int u = tid + t * 256;
        const int row = u >> 3, c = u & 7;
        cpasync16(sbuf + sw128(row * 128 + c * 16),
                  A + (size_t)(bm + row) * K + k0 + c * 8);
    }
#pragma unroll
    for (int t = 0; t < 8; t++) {
        const int u = tid + t * 256;
        const int row = u >> 3, c = u & 7;
        cpasync16(sbuf + LN_ATILE + sw128(row * 128 + c * 16),
                  W + (size_t)(row) * K + k0 + c * 8);
    }
}

__global__ void __launch_bounds__(256, 2)
ln2_kernel(const __half* __restrict__ A16, const __half* __restrict__ W,
           const __half* __restrict__ Rh,
           const float* __restrict__ g, const float* __restrict__ b,
           float* __restrict__ Y, int K)
{
    extern __shared__ char smem[];
    const uint32_t sb = smem_u32(smem);
    const int tid = threadIdx.x;
    const int wid = tid >> 5, lane = tid & 31;
    const int bm = blockIdx.x * 64;
    const int WM = (wid & 1) * 32;
    const int WN = (wid >> 1) * 64;
    const int wq = wid >> 1;
    const int nch = K >> 6;

    float acc[2][8][4];
#pragma unroll
    for (int mi = 0; mi < 2; mi++)
#pragma unroll
        for (int ni = 0; ni < 8; ni++)
#pragma unroll
            for (int j = 0; j < 4; j++) acc[mi][ni][j] = 0.f;

    load_chunk_ln2(A16, W, bm, K, 0, sb, tid);
    asm volatile("cp.async.commit_group;" ::: "memory");

    for (int c = 0; c < nch; c++) {
        if (c + 1 < nch) {
            load_chunk_ln2(A16, W, bm, K, (c + 1) * 64, sb + ((c + 1) & 1) * LN_CH, tid);
            asm volatile("cp.async.commit_group;" ::: "memory");
            asm volatile("cp.async.wait_group 1;" ::: "memory");
        } else {
            asm volatile("cp.async.wait_group 0;" ::: "memory");
        }
        __syncthreads();

        const uint32_t st = sb + (c & 1) * LN_CH;
#pragma unroll
        for (int ks = 0; ks < 4; ks++) {
            const uint32_t cofs = ks * 32 + (lane >> 4) * 16;
            uint32_t a[2][4];
#pragma unroll
            for (int mi = 0; mi < 2; mi++) {
                const uint32_t ro = sw128((WM + mi * 16 + (lane & 15)) * 128 + cofs);
                LDSM4(a[mi][0], a[mi][1], a[mi][2], a[mi][3], st + ro);
            }
#pragma unroll
            for (int np = 0; np < 4; np++) {
                const uint32_t ro = sw128((WN + np * 16 + (lane & 15)) * 128 + cofs);
                uint32_t r0, r1, r2, r3;
                LDSM4(r0, r1, r2, r3, st + LN_ATILE + ro);
                uint32_t bb[2][2];
                bb[0][0] = r0; bb[0][1] = r2;
                bb[1][0] = r1; bb[1][1] = r3;
#pragma unroll
                for (int mi = 0; mi < 2; mi++)
#pragma unroll
                    for (int cc = 0; cc < 2; cc++)
                        MMA16816(acc[mi][np * 2 + cc], a[mi], bb[cc]);
            }
        }
        __syncthreads();
    }

#pragma unroll
    for (int mi = 0; mi < 2; mi++)
#pragma unroll
        for (int h = 0; h < 2; h++) {
            const int row = WM + mi * 16 + h * 8 + (lane >> 2);
#pragma unroll
            for (int ni = 0; ni < 8; ni++) {
                const int col = WN + ni * 8 + (lane & 3) * 2;
                float2 f = __half22float2(*(const __half2*)(Rh + (size_t)(bm + row) * D + col));
                acc[mi][ni][h * 2 + 0] += f.x;
                acc[mi][ni][h * 2 + 1] += f.y;
            }
        }

    float* sp = (float*)(smem + 2 * LN_CH);
#pragma unroll
    for (int mi = 0; mi < 2; mi++)
#pragma unroll
        for (int h = 0; h < 2; h++) {
            float s1 = 0.f, s2 = 0.f;
#pragma unroll
            for (int ni = 0; ni < 8; ni++) {
                float vx = acc[mi][ni][h * 2], vy = acc[mi][ni][h * 2 + 1];
                s1 += vx + vy;
                s2 += vx * vx + vy * vy;
            }
#pragma unroll
            for (int o = 1; o < 4; o <<= 1) {
                s1 += __shfl_xor_sync(0xffffffffu, s1, o);
                s2 += __shfl_xor_sync(0xffffffffu, s2, o);
            }
            if ((lane & 3) == 0) {
                const int row = WM + mi * 16 + h * 8 + (lane >> 2);
                sp[(row * 4 + wq) * 2 + 0] = s1;
                sp[(row * 4 + wq) * 2 + 1] = s2;
            }
        }
    __syncthreads();

#pragma unroll
    for (int mi = 0; mi < 2; mi++)
#pragma unroll
        for (int h = 0; h < 2; h++) {
            const int row = WM + mi * 16 + h * 8 + (lane >> 2);
            float s1 = 0.f, s2 = 0.f;
#pragma unroll
            for (int q = 0; q < 4; q++) {
                s1 += sp[(row * 4 + q) * 2 + 0];
                s2 += sp[(row * 4 + q) * 2 + 1];
            }
            const float mean = s1 * (1.0f / D);
            const float var  = s2 * (1.0f / D) - mean * mean;
            const float rstd = rsqrtf(var + LN_EPS);
#pragma unroll
            for (int ni = 0; ni < 8; ni++) {
                const int col = WN + ni * 8 + (lane & 3) * 2;
                const float2 gg = *(const float2*)(g + col);
                const float2 bb = *(const float2*)(b + col);
                float2 f;
                f.x = (acc[mi][ni][h * 2]     - mean) * rstd * gg.x + bb.x;
                f.y = (acc[mi][ni][h * 2 + 1] - mean) * rstd * gg.y + bb.y;
                *(float2*)(Y + (size_t)(bm + row) * D + col) = f;
            }
        }
}

// ---------------- launch ----------------------------------------------------
extern "C" void kernel_launch(void* const* d_in, const int* in_sizes, int n_in,
                              void* d_out, int out_size)
{
    const float* x      = (const float*)d_in[0];
    const float* W_qkv  = (const float*)d_in[2];
    const float* W_o    = (const float*)d_in[3];
    const float* ln1_g  = (const float*)d_in[4];
    const float* ln1_b  = (const float*)d_in[5];
    const float* W_i    = (const float*)d_in[6];
    const float* W_out2 = (const float*)d_in[7];
    const float* ln2_g  = (const float*)d_in[8];
    const float* ln2_b  = (const float*)d_in[9];
    float* out = (float*)d_out;

    __half *X16, *qkv16, *pre16, *inter16;
    __half *Wq16, *Wo16, *Wi16, *W216;
    cudaGetSymbolAddress((void**)&X16, g_X16);
    cudaGetSymbolAddress((void**)&qkv16, g_qkv16);
    cudaGetSymbolAddress((void**)&pre16, g_pre16);
    cudaGetSymbolAddress((void**)&inter16, g_inter16);
    cudaGetSymbolAddress((void**)&Wq16, g_Wqkv16);
    cudaGetSymbolAddress((void**)&Wo16, g_Wo16);
    cudaGetSymbolAddress((void**)&Wi16, g_Wi16);
    cudaGetSymbolAddress((void**)&W216, g_W216);

    cudaFuncSetAttribute(gemm_mma<0>, cudaFuncAttributeMaxDynamicSharedMemorySize, GSMEM);
    cudaFuncSetAttribute(gemm_mma<2>, cudaFuncAttributeMaxDynamicSharedMemorySize, GSMEM);
    cudaFuncSetAttribute(attn_ln1_kernel, cudaFuncAttributeMaxDynamicSharedMemorySize, AL_SMEM);
    cudaFuncSetAttribute(ln2_kernel, cudaFuncAttributeMaxDynamicSharedMemorySize, LN_SMEM);

    // 0) prep: weight transposes + X conversion (one launch)
    prep_kernel<<<768 + NV * D / 1024, 256>>>(x, W_qkv, W_o, W_i, W_out2,
                                              X16, Wq16, Wo16, Wi16, W216);

    // 1) qkv16 = X @ W_qkv        [16384, 768] fp16
    gemm_mma<0><<<dim3(D_QKV / 128, NV / 128), 256, GSMEM>>>(X16, Wq16, qkv16, D_QKV, D);
    // 2+3+4) pre16 = LN1(attn(qkv) @ W_o + X)   [fused, W-resident]
    attn_ln1_kernel<<<128, 256, AL_SMEM>>>(qkv16, Wo16, x, ln1_g, ln1_b, pre16);
    // 5) inter16 = gelu(pre @ W_i)
    gemm_mma<2><<<dim3(DI / 128, NV / 128), 256, GSMEM>>>(pre16, Wi16, inter16, DI, D);
    // 6+7) out = LN2(inter @ W_out2 + pre16)
    ln2_kernel<<<NV / 64, 256, LN_SMEM>>>(inter16, W216, pre16, ln2_g, ln2_b, out, DI);
}